// round 1
// baseline (speedup 1.0000x reference)
#include <cuda_runtime.h>
#include <cstdint>

// Problem constants
#define T_STEPS 1024
#define BATCH   32
#define DIM     1024
#define NH      64
#define NTOT    256                 // 4 * NH (k | v | q | ax)
#define M_TOTAL (T_STEPS * BATCH)   // 32768

// Scratch for projections: Y[m][c*64+n], m = t*BATCH + b   (32 MB)
__device__ float g_y[(size_t)M_TOTAL * NTOT];

// ---------------- GEMM (tf32 mma.sync) ----------------
#define BM 128
#define BK 16
#define STAGES 3
#define XS_STRIDE 20                       // padded row stride (floats), 16B aligned, conflict-free
#define X_TILE_F (BM * XS_STRIDE)          // 2560 floats
#define W_TILE_F (NTOT * XS_STRIDE)        // 5120 floats
#define STAGE_F  (X_TILE_F + W_TILE_F)     // 7680 floats
#define SMEM_BYTES (STAGES * STAGE_F * 4)  // 92160 B

__device__ __forceinline__ void cp_async16(uint32_t saddr, const void* gptr) {
    asm volatile("cp.async.cg.shared.global [%0], [%1], 16;\n" :: "r"(saddr), "l"(gptr));
}
__device__ __forceinline__ uint32_t f2tf32(float f) {
    uint32_t r;
    asm("cvt.rna.tf32.f32 %0, %1;" : "=r"(r) : "f"(f));
    return r;
}
__device__ __forceinline__ void mma_tf32(float* c, const uint32_t* a, const uint32_t* b) {
    asm volatile(
        "mma.sync.aligned.m16n8k8.row.col.f32.tf32.tf32.f32 "
        "{%0,%1,%2,%3}, {%4,%5,%6,%7}, {%8,%9}, {%0,%1,%2,%3};"
        : "+f"(c[0]), "+f"(c[1]), "+f"(c[2]), "+f"(c[3])
        : "r"(a[0]), "r"(a[1]), "r"(a[2]), "r"(a[3]), "r"(b[0]), "r"(b[1]));
}

__global__ __launch_bounds__(256, 1)
void proj_gemm(const float* __restrict__ X,
               const float* __restrict__ Wk, const float* __restrict__ Wv,
               const float* __restrict__ Wq, const float* __restrict__ Wa)
{
    extern __shared__ float smem[];
    const int tid = threadIdx.x;
    const int m0  = blockIdx.x * BM;

    const float* wptr[4] = {Wk, Wv, Wq, Wa};

    // Per-thread load descriptors (X: 2x float4/stage, W: 4x float4/stage)
    const float* xg[2];
    uint32_t xs_off[2];
#pragma unroll
    for (int l = 0; l < 2; l++) {
        int f = tid + l * 256;
        int row = f >> 2, c4 = f & 3;
        xg[l] = X + (size_t)(m0 + row) * DIM + c4 * 4;
        xs_off[l] = (uint32_t)(row * XS_STRIDE + c4 * 4);
    }
    const float* wg[4];
    uint32_t ws_off[4];
#pragma unroll
    for (int l = 0; l < 4; l++) {
        int f = tid + l * 256;
        int row = f >> 2, c4 = f & 3;
        wg[l] = wptr[row >> 6] + (size_t)(row & 63) * DIM + c4 * 4;
        ws_off[l] = (uint32_t)(X_TILE_F + row * XS_STRIDE + c4 * 4);
    }
    uint32_t smem_base = (uint32_t)__cvta_generic_to_shared(smem);

    const int lane = tid & 31;
    const int w    = tid >> 5;
    const int g    = lane >> 2;   // group id 0..7
    const int q    = lane & 3;    // thread-in-group 0..3
    const int wm   = w >> 2;      // 0..1 : 64-row slab
    const int wn   = w & 3;       // 0..3 : 64-col slab

    float acc[4][8][4];
#pragma unroll
    for (int mi = 0; mi < 4; mi++)
#pragma unroll
        for (int ni = 0; ni < 8; ni++)
#pragma unroll
            for (int r = 0; r < 4; r++) acc[mi][ni][r] = 0.0f;

    const int NITER = DIM / BK;  // 64

    // Prologue: issue STAGES-1 stages
#pragma unroll
    for (int s = 0; s < STAGES - 1; s++) {
        uint32_t sb = smem_base + (uint32_t)((s % STAGES) * STAGE_F * 4);
        int koff = s * BK;
#pragma unroll
        for (int l = 0; l < 2; l++) cp_async16(sb + xs_off[l] * 4, xg[l] + koff);
#pragma unroll
        for (int l = 0; l < 4; l++) cp_async16(sb + ws_off[l] * 4, wg[l] + koff);
        asm volatile("cp.async.commit_group;\n");
    }

    for (int k = 0; k < NITER; k++) {
        asm volatile("cp.async.wait_group %0;\n" :: "n"(STAGES - 2));
        __syncthreads();

        // Issue load for stage k+STAGES-1 (buffer was consumed at iter k-1)
        int nk = k + STAGES - 1;
        if (nk < NITER) {
            uint32_t sb = smem_base + (uint32_t)((nk % STAGES) * STAGE_F * 4);
            int koff = nk * BK;
#pragma unroll
            for (int l = 0; l < 2; l++) cp_async16(sb + xs_off[l] * 4, xg[l] + koff);
#pragma unroll
            for (int l = 0; l < 4; l++) cp_async16(sb + ws_off[l] * 4, wg[l] + koff);
        }
        asm volatile("cp.async.commit_group;\n");

        const float* Xs = smem + (k % STAGES) * STAGE_F;
        const float* Ws = Xs + X_TILE_F;

#pragma unroll
        for (int kk = 0; kk < BK; kk += 8) {
            uint32_t a[4][4], bf[8][2];
#pragma unroll
            for (int mi = 0; mi < 4; mi++) {
                int r = wm * 64 + mi * 16 + g;
                a[mi][0] = f2tf32(Xs[r * XS_STRIDE + kk + q]);
                a[mi][1] = f2tf32(Xs[(r + 8) * XS_STRIDE + kk + q]);
                a[mi][2] = f2tf32(Xs[r * XS_STRIDE + kk + q + 4]);
                a[mi][3] = f2tf32(Xs[(r + 8) * XS_STRIDE + kk + q + 4]);
            }
#pragma unroll
            for (int ni = 0; ni < 8; ni++) {
                int r = wn * 64 + ni * 8 + g;
                bf[ni][0] = f2tf32(Ws[r * XS_STRIDE + kk + q]);
                bf[ni][1] = f2tf32(Ws[r * XS_STRIDE + kk + q + 4]);
            }
#pragma unroll
            for (int mi = 0; mi < 4; mi++)
#pragma unroll
                for (int ni = 0; ni < 8; ni++)
                    mma_tf32(acc[mi][ni], a[mi], bf[ni]);
        }
    }

    // Epilogue: write Y
#pragma unroll
    for (int mi = 0; mi < 4; mi++) {
#pragma unroll
        for (int ni = 0; ni < 8; ni++) {
            int m = m0 + wm * 64 + mi * 16 + g;
            int c = wn * 64 + ni * 8 + q * 2;
            float2 v0 = make_float2(acc[mi][ni][0], acc[mi][ni][1]);
            float2 v1 = make_float2(acc[mi][ni][2], acc[mi][ni][3]);
            *reinterpret_cast<float2*>(&g_y[(size_t)m * NTOT + c]) = v0;
            *reinterpret_cast<float2*>(&g_y[(size_t)(m + 8) * NTOT + c]) = v1;
        }
    }
}

// ---------------- Sequential scan: one warp per (b, row) ----------------
__device__ __forceinline__ float warp_sum(float v) {
    v += __shfl_xor_sync(0xffffffffu, v, 16);
    v += __shfl_xor_sync(0xffffffffu, v, 8);
    v += __shfl_xor_sync(0xffffffffu, v, 4);
    v += __shfl_xor_sync(0xffffffffu, v, 2);
    v += __shfl_xor_sync(0xffffffffu, v, 1);
    return v;
}

__global__ __launch_bounds__(512, 1)
void scan_kernel(const float* __restrict__ S0,
                 const float* __restrict__ d_alpha,
                 const float* __restrict__ b_alpha,
                 float* __restrict__ out, int out_size)
{
    const int b    = blockIdx.y;
    const int warp = threadIdx.x >> 5;
    const int i    = blockIdx.x * 16 + warp;   // row index 0..63
    const int lane = threadIdx.x & 31;

    float s0 = S0[((size_t)b * NH + i) * NH + lane];
    float s1 = S0[((size_t)b * NH + i) * NH + 32 + lane];
    const float da  = d_alpha[i];
    const float bap = b_alpha[i];
    const float* __restrict__ y = g_y;

    // Preload t = 0
    int base = b * NTOT;
    float kj  = y[base + lane];
    float kj2 = y[base + 32 + lane];
    float vi  = y[base + 64 + i];
    float qj  = y[base + 128 + lane];
    float qj2 = y[base + 160 + lane];
    float axi = y[base + 192 + i];

    for (int t = 0; t < T_STEPS; t++) {
        // Software prefetch for t+1 (off the critical path)
        float nkj = 0.f, nkj2 = 0.f, nvi = 0.f, nqj = 0.f, nqj2 = 0.f, naxi = 0.f;
        if (t + 1 < T_STEPS) {
            int nb = ((t + 1) * BATCH + b) * NTOT;
            nkj  = y[nb + lane];
            nkj2 = y[nb + 32 + lane];
            nvi  = y[nb + 64 + i];
            nqj  = y[nb + 128 + lane];
            nqj2 = y[nb + 160 + lane];
            naxi = y[nb + 192 + i];
        }

        // retrieved = S_row . k
        float r = warp_sum(s0 * kj + s1 * kj2);
        float z = fmaf(da, r, axi + bap);
        float alpha = 1.0f / (1.0f + __expf(-z));
        float c = (1.0f - alpha) * vi;
        s0 = fmaf(alpha, s0, c * kj);
        s1 = fmaf(alpha, s1, c * kj2);

        // h = S_row . q ; out = h * silu(h)
        float h = warp_sum(s0 * qj + s1 * qj2);
        if (lane == 0) {
            float sg = 1.0f / (1.0f + __expf(-h));
            out[((size_t)t * BATCH + b) * NH + i] = h * h * sg;
        }

        kj = nkj; kj2 = nkj2; vi = nvi; qj = nqj; qj2 = nqj2; axi = naxi;
    }

    // S_final appended after output
    if (out_size >= T_STEPS * BATCH * NH + BATCH * NH * NH) {
        float* sf = out + (size_t)T_STEPS * BATCH * NH;
        sf[((size_t)b * NH + i) * NH + lane]      = s0;
        sf[((size_t)b * NH + i) * NH + 32 + lane] = s1;
    }
}

extern "C" void kernel_launch(void* const* d_in, const int* in_sizes, int n_in,
                              void* d_out, int out_size)
{
    const float* x  = (const float*)d_in[0];
    const float* S0 = (const float*)d_in[1];
    const float* Wk = (const float*)d_in[2];
    const float* Wv = (const float*)d_in[3];
    const float* Wq = (const float*)d_in[4];
    const float* Wa = (const float*)d_in[5];
    const float* da = (const float*)d_in[6];
    const float* ba = (const float*)d_in[7];
    float* out = (float*)d_out;

    cudaFuncSetAttribute(proj_gemm, cudaFuncAttributeMaxDynamicSharedMemorySize, SMEM_BYTES);

    proj_gemm<<<M_TOTAL / BM, 256, SMEM_BYTES>>>(x, Wk, Wv, Wq, Wa);
    scan_kernel<<<dim3(4, BATCH), 512>>>(S0, da, ba, out, out_size);
}

// round 2
// speedup vs baseline: 1.1290x; 1.1290x over previous
#include <cuda_runtime.h>
#include <cstdint>

// Problem constants
#define T_STEPS 1024
#define BATCH   32
#define DIM     1024
#define NH      64
#define NTOT    256                 // 4 * NH (k | v | q | ax)
#define M_TOTAL (T_STEPS * BATCH)   // 32768

// Scratch for projections: Y[m][c*64+n], m = t*BATCH + b   (32 MB)
__device__ float g_y[(size_t)M_TOTAL * NTOT];

// ---------------- GEMM (tf32 mma.sync) ----------------
#define BM 128
#define BK 16
#define STAGES 3
#define XS_STRIDE 20
#define X_TILE_F (BM * XS_STRIDE)
#define W_TILE_F (NTOT * XS_STRIDE)
#define STAGE_F  (X_TILE_F + W_TILE_F)
#define SMEM_BYTES (STAGES * STAGE_F * 4)

__device__ __forceinline__ void cp_async16(uint32_t saddr, const void* gptr) {
    asm volatile("cp.async.cg.shared.global [%0], [%1], 16;\n" :: "r"(saddr), "l"(gptr));
}
__device__ __forceinline__ uint32_t f2tf32(float f) {
    uint32_t r;
    asm("cvt.rna.tf32.f32 %0, %1;" : "=r"(r) : "f"(f));
    return r;
}
__device__ __forceinline__ void mma_tf32(float* c, const uint32_t* a, const uint32_t* b) {
    asm volatile(
        "mma.sync.aligned.m16n8k8.row.col.f32.tf32.tf32.f32 "
        "{%0,%1,%2,%3}, {%4,%5,%6,%7}, {%8,%9}, {%0,%1,%2,%3};"
        : "+f"(c[0]), "+f"(c[1]), "+f"(c[2]), "+f"(c[3])
        : "r"(a[0]), "r"(a[1]), "r"(a[2]), "r"(a[3]), "r"(b[0]), "r"(b[1]));
}

__global__ __launch_bounds__(256, 1)
void proj_gemm(const float* __restrict__ X,
               const float* __restrict__ Wk, const float* __restrict__ Wv,
               const float* __restrict__ Wq, const float* __restrict__ Wa)
{
    extern __shared__ float smem[];
    const int tid = threadIdx.x;
    const int m0  = blockIdx.x * BM;

    const float* wptr[4] = {Wk, Wv, Wq, Wa};

    const float* xg[2];
    uint32_t xs_off[2];
#pragma unroll
    for (int l = 0; l < 2; l++) {
        int f = tid + l * 256;
        int row = f >> 2, c4 = f & 3;
        xg[l] = X + (size_t)(m0 + row) * DIM + c4 * 4;
        xs_off[l] = (uint32_t)(row * XS_STRIDE + c4 * 4);
    }
    const float* wg[4];
    uint32_t ws_off[4];
#pragma unroll
    for (int l = 0; l < 4; l++) {
        int f = tid + l * 256;
        int row = f >> 2, c4 = f & 3;
        wg[l] = wptr[row >> 6] + (size_t)(row & 63) * DIM + c4 * 4;
        ws_off[l] = (uint32_t)(X_TILE_F + row * XS_STRIDE + c4 * 4);
    }
    uint32_t smem_base = (uint32_t)__cvta_generic_to_shared(smem);

    const int lane = tid & 31;
    const int w    = tid >> 5;
    const int g    = lane >> 2;
    const int q    = lane & 3;
    const int wm   = w >> 2;
    const int wn   = w & 3;

    float acc[4][8][4];
#pragma unroll
    for (int mi = 0; mi < 4; mi++)
#pragma unroll
        for (int ni = 0; ni < 8; ni++)
#pragma unroll
            for (int r = 0; r < 4; r++) acc[mi][ni][r] = 0.0f;

    const int NITER = DIM / BK;

#pragma unroll
    for (int s = 0; s < STAGES - 1; s++) {
        uint32_t sb = smem_base + (uint32_t)((s % STAGES) * STAGE_F * 4);
        int koff = s * BK;
#pragma unroll
        for (int l = 0; l < 2; l++) cp_async16(sb + xs_off[l] * 4, xg[l] + koff);
#pragma unroll
        for (int l = 0; l < 4; l++) cp_async16(sb + ws_off[l] * 4, wg[l] + koff);
        asm volatile("cp.async.commit_group;\n");
    }

    for (int k = 0; k < NITER; k++) {
        asm volatile("cp.async.wait_group %0;\n" :: "n"(STAGES - 2));
        __syncthreads();

        int nk = k + STAGES - 1;
        if (nk < NITER) {
            uint32_t sb = smem_base + (uint32_t)((nk % STAGES) * STAGE_F * 4);
            int koff = nk * BK;
#pragma unroll
            for (int l = 0; l < 2; l++) cp_async16(sb + xs_off[l] * 4, xg[l] + koff);
#pragma unroll
            for (int l = 0; l < 4; l++) cp_async16(sb + ws_off[l] * 4, wg[l] + koff);
        }
        asm volatile("cp.async.commit_group;\n");

        const float* Xs = smem + (k % STAGES) * STAGE_F;
        const float* Ws = Xs + X_TILE_F;

#pragma unroll
        for (int kk = 0; kk < BK; kk += 8) {
            uint32_t a[4][4], bf[8][2];
#pragma unroll
            for (int mi = 0; mi < 4; mi++) {
                int r = wm * 64 + mi * 16 + g;
                a[mi][0] = f2tf32(Xs[r * XS_STRIDE + kk + q]);
                a[mi][1] = f2tf32(Xs[(r + 8) * XS_STRIDE + kk + q]);
                a[mi][2] = f2tf32(Xs[r * XS_STRIDE + kk + q + 4]);
                a[mi][3] = f2tf32(Xs[(r + 8) * XS_STRIDE + kk + q + 4]);
            }
#pragma unroll
            for (int ni = 0; ni < 8; ni++) {
                int r = wn * 64 + ni * 8 + g;
                bf[ni][0] = f2tf32(Ws[r * XS_STRIDE + kk + q]);
                bf[ni][1] = f2tf32(Ws[r * XS_STRIDE + kk + q + 4]);
            }
#pragma unroll
            for (int mi = 0; mi < 4; mi++)
#pragma unroll
                for (int ni = 0; ni < 8; ni++)
                    mma_tf32(acc[mi][ni], a[mi], bf[ni]);
        }
    }

#pragma unroll
    for (int mi = 0; mi < 4; mi++) {
#pragma unroll
        for (int ni = 0; ni < 8; ni++) {
            int m = m0 + wm * 64 + mi * 16 + g;
            int c = wn * 64 + ni * 8 + q * 2;
            float2 v0 = make_float2(acc[mi][ni][0], acc[mi][ni][1]);
            float2 v1 = make_float2(acc[mi][ni][2], acc[mi][ni][3]);
            *reinterpret_cast<float2*>(&g_y[(size_t)m * NTOT + c]) = v0;
            *reinterpret_cast<float2*>(&g_y[(size_t)(m + 8) * NTOT + c]) = v1;
        }
    }
}

// ---------------- Scan v2: 16 lanes/row, 2 rows/warp, pipelined recurrence ----------------
// Per (b,i): s evolves as s' = a*s + c*k. We carry rk = s·k via the algebraic
// recurrence rk(t+1) = a_t*(s(t)·k(t+1)) + c_t*(k(t)·k(t+1)) so the butterfly
// reduction for step t+1's alpha starts one full iteration early.

__device__ __forceinline__ float bfly16(float v) {
    v += __shfl_xor_sync(0xffffffffu, v, 8);
    v += __shfl_xor_sync(0xffffffffu, v, 4);
    v += __shfl_xor_sync(0xffffffffu, v, 2);
    v += __shfl_xor_sync(0xffffffffu, v, 1);
    return v;
}
__device__ __forceinline__ float dot4(float4 a, float4 b) {
    return fmaf(a.x, b.x, a.y * b.y) + fmaf(a.z, b.z, a.w * b.w);
}
__device__ __forceinline__ float sigmoidf_(float z) {
    return 1.0f / (1.0f + __expf(-z));
}

__global__ __launch_bounds__(256, 1)
void scan_kernel(const float* __restrict__ S0,
                 const float* __restrict__ d_alpha,
                 const float* __restrict__ b_alpha,
                 float* __restrict__ out)
{
    const int b    = blockIdx.y;
    const int lane = threadIdx.x & 31;
    const int warp = threadIdx.x >> 5;                       // 0..7
    const int i    = blockIdx.x * 16 + warp * 2 + (lane >> 4); // row 0..63
    const int j16  = lane & 15;
    const int c0   = j16 * 4;                                 // column base

    const float* __restrict__ y = g_y;

    float4 s = *reinterpret_cast<const float4*>(&S0[((size_t)b * NH + i) * NH + c0]);
    const float da  = d_alpha[i];
    const float bap = b_alpha[i];

    // Rotating 4-slot prefetch buffers (slot = t & 3), preload t = 0..2
    float4 kb[4], qb[4];
    float  vb[4], ab[4];
#pragma unroll
    for (int s0i = 0; s0i < 4; s0i++) {
        kb[s0i] = make_float4(0.f, 0.f, 0.f, 0.f);
        qb[s0i] = make_float4(0.f, 0.f, 0.f, 0.f);
        vb[s0i] = 0.f; ab[s0i] = 0.f;
    }
#pragma unroll
    for (int tp = 0; tp < 3; tp++) {
        int base = (tp * BATCH + b) * NTOT;
        kb[tp] = *reinterpret_cast<const float4*>(&y[base + c0]);
        qb[tp] = *reinterpret_cast<const float4*>(&y[base + 128 + c0]);
        vb[tp] = y[base + 64 + i];
        ab[tp] = y[base + 192 + i];
    }

    float rk = bfly16(dot4(s, kb[0]));

    float* __restrict__ out_bi = out + b * NH + i;

#pragma unroll 4
    for (int t = 0; t < T_STEPS; t++) {
        const int cs = t & 3;          // current slot
        const int ns = (t + 1) & 3;    // next slot (k_{t+1})
        const int ls = (t + 3) & 3;    // slot to fill with t+3

        // Prefetch t+3 (3-iteration window covers L2 latency)
        if (t + 3 < T_STEPS) {
            int base = ((t + 3) * BATCH + b) * NTOT;
            kb[ls] = *reinterpret_cast<const float4*>(&y[base + c0]);
            qb[ls] = *reinterpret_cast<const float4*>(&y[base + 128 + c0]);
            vb[ls] = y[base + 64 + i];
            ab[ls] = y[base + 192 + i];
        }

        // alpha from carried rk (reduction finished last iteration)
        float z     = fmaf(da, rk, ab[cs] + bap);
        float alpha = sigmoidf_(z);
        float c     = (1.0f - alpha) * vb[cs];

        // Launch next-step reductions early (use PRE-update s)
        float la = dot4(s, kb[ns]);        // A = s(t)·k(t+1)
        float lb = dot4(kb[cs], kb[ns]);   // B = k(t)·k(t+1)
        float A  = bfly16(la);
        float B  = bfly16(lb);

        // State update: s = alpha*s + c*k(t)
        s.x = fmaf(alpha, s.x, c * kb[cs].x);
        s.y = fmaf(alpha, s.y, c * kb[cs].y);
        s.z = fmaf(alpha, s.z, c * kb[cs].z);
        s.w = fmaf(alpha, s.w, c * kb[cs].w);

        // h = s_new · q(t); out = h * silu(h)   (off recurrence path)
        float h = bfly16(dot4(s, qb[cs]));
        if (j16 == 0) {
            float sg = sigmoidf_(h);
            out_bi[(size_t)t * (BATCH * NH)] = h * h * sg;
        }

        // Carry rk for t+1
        rk = fmaf(alpha, A, c * B);
    }

    // S_final appended after output
    float* sf = out + (size_t)T_STEPS * BATCH * NH;
    *reinterpret_cast<float4*>(&sf[((size_t)b * NH + i) * NH + c0]) = s;
}

extern "C" void kernel_launch(void* const* d_in, const int* in_sizes, int n_in,
                              void* d_out, int out_size)
{
    const float* x  = (const float*)d_in[0];
    const float* S0 = (const float*)d_in[1];
    const float* Wk = (const float*)d_in[2];
    const float* Wv = (const float*)d_in[3];
    const float* Wq = (const float*)d_in[4];
    const float* Wa = (const float*)d_in[5];
    const float* da = (const float*)d_in[6];
    const float* ba = (const float*)d_in[7];
    float* out = (float*)d_out;
    (void)out_size;

    cudaFuncSetAttribute(proj_gemm, cudaFuncAttributeMaxDynamicSharedMemorySize, SMEM_BYTES);

    proj_gemm<<<M_TOTAL / BM, 256, SMEM_BYTES>>>(x, Wk, Wv, Wq, Wa);
    scan_kernel<<<dim3(4, BATCH), 256>>>(S0, da, ba, out);
}

// round 3
// speedup vs baseline: 1.5068x; 1.3346x over previous
#include <cuda_runtime.h>
#include <cstdint>

// Problem constants
#define T_STEPS 1024
#define BATCH   32
#define DIM     1024
#define NH      64
#define NTOT    256                 // 4 * NH (k | v | q | ax)
#define M_TOTAL (T_STEPS * BATCH)   // 32768

// Scratch: projections Y[m][256], m = t*BATCH+b  (32 MB)
__device__ float g_y[(size_t)M_TOTAL * NTOT];
// Precomputed per-(t,b) dot scalars, 8 floats each (1 MB):
// {KK1[t], KK2[t+1], KK3[t+2], KQ0[t], KQ1[t], KQ2[t+1], KQ3[t+2], 0}
__device__ float g_pc[(size_t)M_TOTAL * 8];

// ---------------- GEMM (tf32 mma.sync) ----------------
#define BM 128
#define BK 16
#define STAGES 3
#define XS_STRIDE 20
#define X_TILE_F (BM * XS_STRIDE)
#define W_TILE_F (NTOT * XS_STRIDE)
#define STAGE_F  (X_TILE_F + W_TILE_F)
#define SMEM_BYTES (STAGES * STAGE_F * 4)

__device__ __forceinline__ void cp_async16(uint32_t saddr, const void* gptr) {
    asm volatile("cp.async.cg.shared.global [%0], [%1], 16;\n" :: "r"(saddr), "l"(gptr));
}
__device__ __forceinline__ uint32_t f2tf32(float f) {
    uint32_t r;
    asm("cvt.rna.tf32.f32 %0, %1;" : "=r"(r) : "f"(f));
    return r;
}
__device__ __forceinline__ void mma_tf32(float* c, const uint32_t* a, const uint32_t* b) {
    asm volatile(
        "mma.sync.aligned.m16n8k8.row.col.f32.tf32.tf32.f32 "
        "{%0,%1,%2,%3}, {%4,%5,%6,%7}, {%8,%9}, {%0,%1,%2,%3};"
        : "+f"(c[0]), "+f"(c[1]), "+f"(c[2]), "+f"(c[3])
        : "r"(a[0]), "r"(a[1]), "r"(a[2]), "r"(a[3]), "r"(b[0]), "r"(b[1]));
}

__global__ __launch_bounds__(256, 1)
void proj_gemm(const float* __restrict__ X,
               const float* __restrict__ Wk, const float* __restrict__ Wv,
               const float* __restrict__ Wq, const float* __restrict__ Wa)
{
    extern __shared__ float smem[];
    const int tid = threadIdx.x;
    const int m0  = blockIdx.x * BM;

    const float* wptr[4] = {Wk, Wv, Wq, Wa};

    const float* xg[2];
    uint32_t xs_off[2];
#pragma unroll
    for (int l = 0; l < 2; l++) {
        int f = tid + l * 256;
        int row = f >> 2, c4 = f & 3;
        xg[l] = X + (size_t)(m0 + row) * DIM + c4 * 4;
        xs_off[l] = (uint32_t)(row * XS_STRIDE + c4 * 4);
    }
    const float* wg[4];
    uint32_t ws_off[4];
#pragma unroll
    for (int l = 0; l < 4; l++) {
        int f = tid + l * 256;
        int row = f >> 2, c4 = f & 3;
        wg[l] = wptr[row >> 6] + (size_t)(row & 63) * DIM + c4 * 4;
        ws_off[l] = (uint32_t)(X_TILE_F + row * XS_STRIDE + c4 * 4);
    }
    uint32_t smem_base = (uint32_t)__cvta_generic_to_shared(smem);

    const int lane = tid & 31;
    const int w    = tid >> 5;
    const int g    = lane >> 2;
    const int q    = lane & 3;
    const int wm   = w >> 2;
    const int wn   = w & 3;

    float acc[4][8][4];
#pragma unroll
    for (int mi = 0; mi < 4; mi++)
#pragma unroll
        for (int ni = 0; ni < 8; ni++)
#pragma unroll
            for (int r = 0; r < 4; r++) acc[mi][ni][r] = 0.0f;

    const int NITER = DIM / BK;

#pragma unroll
    for (int s = 0; s < STAGES - 1; s++) {
        uint32_t sb = smem_base + (uint32_t)((s % STAGES) * STAGE_F * 4);
        int koff = s * BK;
#pragma unroll
        for (int l = 0; l < 2; l++) cp_async16(sb + xs_off[l] * 4, xg[l] + koff);
#pragma unroll
        for (int l = 0; l < 4; l++) cp_async16(sb + ws_off[l] * 4, wg[l] + koff);
        asm volatile("cp.async.commit_group;\n");
    }

    for (int k = 0; k < NITER; k++) {
        asm volatile("cp.async.wait_group %0;\n" :: "n"(STAGES - 2));
        __syncthreads();

        int nk = k + STAGES - 1;
        if (nk < NITER) {
            uint32_t sb = smem_base + (uint32_t)((nk % STAGES) * STAGE_F * 4);
            int koff = nk * BK;
#pragma unroll
            for (int l = 0; l < 2; l++) cp_async16(sb + xs_off[l] * 4, xg[l] + koff);
#pragma unroll
            for (int l = 0; l < 4; l++) cp_async16(sb + ws_off[l] * 4, wg[l] + koff);
        }
        asm volatile("cp.async.commit_group;\n");

        const float* Xs = smem + (k % STAGES) * STAGE_F;
        const float* Ws = Xs + X_TILE_F;

#pragma unroll
        for (int kk = 0; kk < BK; kk += 8) {
            uint32_t a[4][4], bf[8][2];
#pragma unroll
            for (int mi = 0; mi < 4; mi++) {
                int r = wm * 64 + mi * 16 + g;
                a[mi][0] = f2tf32(Xs[r * XS_STRIDE + kk + q]);
                a[mi][1] = f2tf32(Xs[(r + 8) * XS_STRIDE + kk + q]);
                a[mi][2] = f2tf32(Xs[r * XS_STRIDE + kk + q + 4]);
                a[mi][3] = f2tf32(Xs[(r + 8) * XS_STRIDE + kk + q + 4]);
            }
#pragma unroll
            for (int ni = 0; ni < 8; ni++) {
                int r = wn * 64 + ni * 8 + g;
                bf[ni][0] = f2tf32(Ws[r * XS_STRIDE + kk + q]);
                bf[ni][1] = f2tf32(Ws[r * XS_STRIDE + kk + q + 4]);
            }
#pragma unroll
            for (int mi = 0; mi < 4; mi++)
#pragma unroll
                for (int ni = 0; ni < 8; ni++)
                    mma_tf32(acc[mi][ni], a[mi], bf[ni]);
        }
    }

#pragma unroll
    for (int mi = 0; mi < 4; mi++) {
#pragma unroll
        for (int ni = 0; ni < 8; ni++) {
            int m = m0 + wm * 64 + mi * 16 + g;
            int c = wn * 64 + ni * 8 + q * 2;
            float2 v0 = make_float2(acc[mi][ni][0], acc[mi][ni][1]);
            float2 v1 = make_float2(acc[mi][ni][2], acc[mi][ni][3]);
            *reinterpret_cast<float2*>(&g_y[(size_t)m * NTOT + c]) = v0;
            *reinterpret_cast<float2*>(&g_y[(size_t)(m + 8) * NTOT + c]) = v1;
        }
    }
}

// ---------------- Precompute k.k / k.q scalars ----------------
__device__ __forceinline__ float wsum32(float v) {
    v += __shfl_xor_sync(0xffffffffu, v, 16);
    v += __shfl_xor_sync(0xffffffffu, v, 8);
    v += __shfl_xor_sync(0xffffffffu, v, 4);
    v += __shfl_xor_sync(0xffffffffu, v, 2);
    v += __shfl_xor_sync(0xffffffffu, v, 1);
    return v;
}

__global__ __launch_bounds__(256, 2)
void precomp_kernel()
{
    int gw = (blockIdx.x * blockDim.x + threadIdx.x) >> 5;   // 0..32767
    int lane = threadIdx.x & 31;
    int t = gw >> 5, b = gw & 31;
    int e = lane * 2;

    const float* y = g_y;
    auto ldk = [&](int tt) -> float2 {
        return *reinterpret_cast<const float2*>(&y[(size_t)(tt * BATCH + b) * NTOT + e]);
    };
    auto ldq = [&](int tt) -> float2 {
        return *reinterpret_cast<const float2*>(&y[(size_t)(tt * BATCH + b) * NTOT + 128 + e]);
    };

    int t1 = t + 1 < T_STEPS ? t + 1 : T_STEPS - 1;
    int t2 = t + 2 < T_STEPS ? t + 2 : T_STEPS - 1;

    float2 km1 = (t > 0) ? ldk(t - 1) : make_float2(0.f, 0.f);
    float2 k0 = ldk(t), k1 = ldk(t1), k2 = ldk(t2);
    float2 q0 = ldq(t), q1 = ldq(t1), q2 = ldq(t2);

    float kk1 = wsum32(fmaf(km1.x, k0.x, km1.y * k0.y));
    float kk2 = wsum32(fmaf(km1.x, k1.x, km1.y * k1.y));
    float kk3 = wsum32(fmaf(km1.x, k2.x, km1.y * k2.y));
    float kq0 = wsum32(fmaf(k0.x,  q0.x, k0.y  * q0.y));
    float kq1 = wsum32(fmaf(km1.x, q0.x, km1.y * q0.y));
    float kq2 = wsum32(fmaf(km1.x, q1.x, km1.y * q1.y));
    float kq3 = wsum32(fmaf(km1.x, q2.x, km1.y * q2.y));

    if (lane == 0) {
        float* p = &g_pc[(size_t)gw * 8];
        *reinterpret_cast<float4*>(p)     = make_float4(kk1, kk2, kk3, kq0);
        *reinterpret_cast<float4*>(p + 4) = make_float4(kq1, kq2, kq3, 0.f);
    }
}

// ---------------- Scan v3: 8 lanes/row, lag-3 recurrence, smem-staged ----------------
#define SLOT_F 168           // per-t smem floats: kq[128] v[16] ax[16] pc[8]
#define RING   32            // t-slots resident (4 groups of 8)

__device__ __forceinline__ float bfly8(float v) {
    v += __shfl_xor_sync(0xffffffffu, v, 4);
    v += __shfl_xor_sync(0xffffffffu, v, 2);
    v += __shfl_xor_sync(0xffffffffu, v, 1);
    return v;
}
__device__ __forceinline__ float dot8(float4 a0, float4 a1, float4 b0, float4 b1) {
    float p = a0.x * b0.x;
    p = fmaf(a0.y, b0.y, p); p = fmaf(a0.z, b0.z, p); p = fmaf(a0.w, b0.w, p);
    p = fmaf(a1.x, b1.x, p); p = fmaf(a1.y, b1.y, p);
    p = fmaf(a1.z, b1.z, p); p = fmaf(a1.w, b1.w, p);
    return p;
}
__device__ __forceinline__ float fsig(float z) {
    return __fdividef(1.0f, 1.0f + __expf(-z));
}

__global__ __launch_bounds__(128, 1)
void scan_kernel(const float* __restrict__ S0,
                 const float* __restrict__ d_alpha,
                 const float* __restrict__ b_alpha,
                 float* __restrict__ out)
{
    __shared__ float sm[RING * SLOT_F];   // 21504 B

    const int tid  = threadIdx.x;
    const int b    = blockIdx.y;
    const int i0   = blockIdx.x * 16;
    const int lane = tid & 31;
    const int w    = tid >> 5;
    const int r    = lane >> 3;           // row-in-warp 0..3
    const int j8   = lane & 7;            // 8 lanes per row
    const int i    = i0 + w * 4 + r;      // global row 0..63
    const int c0   = j8 * 8;              // column base (8 elems/lane)
    const int il   = i - i0;              // 0..15

    // cp.async group issue: 8 consecutive t into the ring (42 float4 chunks/t)
    auto issue_group = [&](int gidx) {
#pragma unroll
        for (int c = tid; c < 336; c += 128) {
            int tl = c / 42, f = c - tl * 42;
            int t  = gidx * 8 + tl;
            int slot = t & (RING - 1);
            int tc = t < T_STEPS ? t : T_STEPS - 1;
            size_t yb = (size_t)(tc * BATCH + b) * NTOT;
            const float* src;
            float* dst = &sm[slot * SLOT_F];
            if (f < 32)      { src = g_y + yb + (f < 16 ? f * 4 : 128 + (f - 16) * 4); dst += f * 4; }
            else if (f < 36) { src = g_y + yb + 64  + i0 + (f - 32) * 4; dst += 128 + (f - 32) * 4; }
            else if (f < 40) { src = g_y + yb + 192 + i0 + (f - 36) * 4; dst += 144 + (f - 36) * 4; }
            else             { src = g_pc + (size_t)(tc * BATCH + b) * 8 + (f - 40) * 4; dst += 160 + (f - 40) * 4; }
            cp_async16((uint32_t)__cvta_generic_to_shared(dst), src);
        }
        asm volatile("cp.async.commit_group;\n");
    };

    issue_group(0);
    issue_group(1);
    issue_group(2);

    float4 s0v = *reinterpret_cast<const float4*>(&S0[((size_t)b * NH + i) * NH + c0]);
    float4 s1v = *reinterpret_cast<const float4*>(&S0[((size_t)b * NH + i) * NH + c0 + 4]);
    const float da  = d_alpha[i];
    const float bap = b_alpha[i];

    asm volatile("cp.async.wait_group 2;\n");
    __syncthreads();

    auto K4 = [&](int t, int c) -> float4 {
        return *reinterpret_cast<const float4*>(&sm[(t & (RING - 1)) * SLOT_F + c]);
    };
    auto Q4 = [&](int t, int c) -> float4 {
        return *reinterpret_cast<const float4*>(&sm[(t & (RING - 1)) * SLOT_F + 64 + c]);
    };

    // Prologue: P3_t = s0.k(t), C3_t = s0.q(t) for t = 0,1,2 (s(-1)=s(-2)=s(-3)=s0)
    float P3_0 = bfly8(dot8(s0v, s1v, K4(0, c0), K4(0, c0 + 4)));
    float P3_1 = bfly8(dot8(s0v, s1v, K4(1, c0), K4(1, c0 + 4)));
    float P3_2 = bfly8(dot8(s0v, s1v, K4(2, c0), K4(2, c0 + 4)));
    float C3_0 = bfly8(dot8(s0v, s1v, Q4(0, c0), Q4(0, c0 + 4)));
    float C3_1 = bfly8(dot8(s0v, s1v, Q4(1, c0), Q4(1, c0 + 4)));
    float C3_2 = bfly8(dot8(s0v, s1v, Q4(2, c0), Q4(2, c0 + 4)));

    // Pipeline registers (conventions: alpha_{<0}=1, c_{<0}=0)
    float a1 = 1.0f, c1 = 0.0f;
    float M2 = P3_0, M1 = P3_1, P3n = P3_2;   // M2_t, M1_{t+1}, P3_{t+2}
    float N2 = C3_0, N1 = C3_1, C3n = C3_2;

    float* __restrict__ out_bi = out + b * NH + i;

    for (int m = 0; m < T_STEPS / 8; m++) {
        asm volatile("cp.async.wait_group 1;\n");
        __syncthreads();

#pragma unroll
        for (int u = 0; u < 8; u++) {
            const int t = m * 8 + u;
            const int slot = t & (RING - 1);
            const float* sp = &sm[slot * SLOT_F];

            // loads (issued early; consumed later — LDS latency hidden by issue distance)
            float4 kc0 = K4(t, c0),     kc1 = K4(t, c0 + 4);        // k(t)
            float4 kp0 = K4(t + 3, c0), kp1 = K4(t + 3, c0 + 4);    // k(t+3)
            float4 qp0 = Q4(t + 3, c0), qp1 = Q4(t + 3, c0 + 4);    // q(t+3)
            float  vt  = sp[128 + il];
            float  axb = sp[144 + il] + bap;
            float4 pA  = *reinterpret_cast<const float4*>(&sp[160]);     // KK1,KK2',KK3'',KQ0
            float4 pB  = *reinterpret_cast<const float4*>(&sp[164]);     // KQ1,KQ2',KQ3'',-

            // launch lag-3 butterflies on PRE-update s: P3_{t+3}, C3_{t+3}
            float P3new = bfly8(dot8(s0v, s1v, kp0, kp1));
            float C3new = bfly8(dot8(s0v, s1v, qp0, qp1));

            // recurrence (critical path): rk -> alpha -> c
            float rk    = fmaf(a1, M2, c1 * pA.x);
            float z     = fmaf(da, rk, axb);
            float alpha = fsig(z);
            float cc    = (1.0f - alpha) * vt;

            // output h = alpha*N3 + c*KQ0  (N3 = a1*N2 + c1*KQ1)
            float N3 = fmaf(a1, N2, c1 * pB.x);
            float h  = fmaf(alpha, N3, cc * pA.w);

            // build future pipeline values (use a1/c1 BEFORE rotation)
            float M1n = fmaf(a1, P3n, c1 * pA.z);      // M1_{t+2}
            float N1n = fmaf(a1, C3n, c1 * pB.z);      // N1_{t+2}
            M2 = fmaf(a1, M1, c1 * pA.y);              // M2_{t+1}
            N2 = fmaf(a1, N1, c1 * pB.y);              // N2_{t+1}
            M1 = M1n; N1 = N1n; P3n = P3new; C3n = C3new;

            // state update: s = alpha*s + c*k(t)
            s0v.x = fmaf(alpha, s0v.x, cc * kc0.x);
            s0v.y = fmaf(alpha, s0v.y, cc * kc0.y);
            s0v.z = fmaf(alpha, s0v.z, cc * kc0.z);
            s0v.w = fmaf(alpha, s0v.w, cc * kc0.w);
            s1v.x = fmaf(alpha, s1v.x, cc * kc1.x);
            s1v.y = fmaf(alpha, s1v.y, cc * kc1.y);
            s1v.z = fmaf(alpha, s1v.z, cc * kc1.z);
            s1v.w = fmaf(alpha, s1v.w, cc * kc1.w);

            a1 = alpha; c1 = cc;

            if (j8 == 0) {
                float sg = fsig(h);
                out_bi[(size_t)t * (BATCH * NH)] = h * h * sg;
            }
        }

        issue_group(m + 3);
    }

    // S_final appended after output
    float* sf = out + (size_t)T_STEPS * BATCH * NH;
    *reinterpret_cast<float4*>(&sf[((size_t)b * NH + i) * NH + c0])     = s0v;
    *reinterpret_cast<float4*>(&sf[((size_t)b * NH + i) * NH + c0 + 4]) = s1v;
}

extern "C" void kernel_launch(void* const* d_in, const int* in_sizes, int n_in,
                              void* d_out, int out_size)
{
    const float* x  = (const float*)d_in[0];
    const float* S0 = (const float*)d_in[1];
    const float* Wk = (const float*)d_in[2];
    const float* Wv = (const float*)d_in[3];
    const float* Wq = (const float*)d_in[4];
    const float* Wa = (const float*)d_in[5];
    const float* da = (const float*)d_in[6];
    const float* ba = (const float*)d_in[7];
    float* out = (float*)d_out;
    (void)out_size;

    cudaFuncSetAttribute(proj_gemm, cudaFuncAttributeMaxDynamicSharedMemorySize, SMEM_BYTES);

    proj_gemm<<<M_TOTAL / BM, 256, SMEM_BYTES>>>(x, Wk, Wv, Wq, Wa);
    precomp_kernel<<<M_TOTAL / 8, 256>>>();
    scan_kernel<<<dim3(4, BATCH), 128>>>(S0, da, ba, out);
}